// round 12
// baseline (speedup 1.0000x reference)
#include <cuda_runtime.h>
#include <cuda_bf16.h>
#include <cstdint>
#include <math.h>

#define BNS 0.9999950000374996f  // 1/sqrt(1+1e-5)

// ================= scratch (device globals) ================================
__device__ float g_k   [32*96*256];
__device__ float g_v   [32*384*256];
__device__ float g_w   [32*4*256];
__device__ float g_q   [4*32*96*256];
__device__ float g_res [4*32*256*384];     // res PRE-acts (E*TB,N,C)
__device__ float g_p   [32*384*256];       // proj PRE-acts
__device__ float g_xr  [32*384*256];
__device__ float g_h   [32*2048*256];
__device__ float g_m   [32*1024*256];
__device__ float g_f2  [32*384*256];       // fc2 PRE-acts
__device__ unsigned short g_qb[128*256*96];
__device__ unsigned short g_kb[32*256*96];
__device__ unsigned short g_vb[32*384*256];
__device__ unsigned short g_ab[128*256*256];
__device__ unsigned short g_yb[32*256*384];
__device__ unsigned short g_mb[32*256*1024];
__device__ unsigned short g_w3a[3*384*384];
__device__ unsigned short g_w3b[3*384*1024];

__device__ __forceinline__ uint32_t smem_u32(const void* p){
    uint32_t a;
    asm("{ .reg .u64 t; cvta.to.shared.u64 t, %1; cvt.u32.u64 %0, t; }" : "=r"(a) : "l"(p));
    return a;
}
#define LDMX4(r0,r1,r2,r3,ad) \
    asm volatile("ldmatrix.sync.aligned.m8n8.x4.shared.b16 {%0,%1,%2,%3}, [%4];" \
        : "=r"(r0),"=r"(r1),"=r"(r2),"=r"(r3) : "r"(ad))
#define LDMX2(r0,r1,ad) \
    asm volatile("ldmatrix.sync.aligned.m8n8.x2.shared.b16 {%0,%1}, [%2];" \
        : "=r"(r0),"=r"(r1) : "r"(ad))
#define MMA16816(c0,c1,c2,c3,a0,a1,a2,a3,b0,b1) \
    asm volatile("mma.sync.aligned.m16n8k16.row.col.f32.bf16.bf16.f32 " \
        "{%0,%1,%2,%3}, {%4,%5,%6,%7}, {%8,%9}, {%0,%1,%2,%3};" \
        : "+f"(c0),"+f"(c1),"+f"(c2),"+f"(c3) \
        : "r"(a0),"r"(a1),"r"(a2),"r"(a3),"r"(b0),"r"(b1))
#define CPA16(dst, src) \
    asm volatile("cp.async.cg.shared.global [%0], [%1], 16;" :: "r"(dst), "l"(src) : "memory")
#define CPA_COMMIT() asm volatile("cp.async.commit_group;" ::: "memory")
#define CPA_WAIT1()  asm volatile("cp.async.wait_group 1;"  ::: "memory")

// ===== SIMT GEMM, S z-slabs share one A tile, cp.async 3-stage pipeline ====
// N fixed 256, B row-major [k][256], A [M][K] k-contiguous.
// slab = g*32 + p + (32/S)*s, p = bz % (32/S), g = bz / (32/S).
// Compute/fma order identical to R9/R10 kernels (bit-exact results).
template<int S>
__global__ __launch_bounds__(256) void gemm_zs_kernel(
    const float* __restrict__ A, long aG,
    const float* __restrict__ B, long bSlab,
    float* __restrict__ C,
    const float* __restrict__ bias, const float* __restrict__ scale,
    const float* __restrict__ shift, int pG,
    int M, int K)
{
    extern __shared__ float sm[];
    float* AsB = sm;               // [3][16][68]
    float* BsB = sm + 3 * 1088;    // [3][S][16][68]
    const int PDIV = 32 / S;
    int bz = blockIdx.z;
    int g = bz / PDIV, p = bz % PDIV;
    const float* Ap = A + (long)g * aG;
    const float* Bp[S];
    #pragma unroll
    for (int s = 0; s < S; s++) Bp[s] = B + (long)(p + PDIV * s) * bSlab;
    int m0 = blockIdx.y * 64, n0 = blockIdx.x * 64;
    int tid = threadIdx.x, tx = tid & 15, ty = tid >> 4;
    int am = tid >> 2, ak = (tid & 3) * 4;
    int bk = tid >> 4, bn = (tid & 15) * 4;
    uint32_t bsu = smem_u32(BsB);
    float acc[S][4][4] = {};
    int nT = K >> 4;

    // prologue: stages 0,1
    #pragma unroll
    for (int st = 0; st < 2; st++) {
        if (st < nT) {
            long boff = (long)(st * 16 + bk) * 256 + n0 + bn;
            #pragma unroll
            for (int s = 0; s < S; s++) {
                uint32_t dst = bsu + (uint32_t)(((((st * S + s) * 16 + bk) * 68 + bn)) * 4);
                CPA16(dst, Bp[s] + boff);
            }
            float4 a4 = make_float4(0.f, 0.f, 0.f, 0.f);
            if (m0 + am < M) a4 = *(const float4*)&Ap[(long)(m0 + am) * K + st * 16 + ak];
            float* as = AsB + st * 1088;
            as[(ak + 0) * 68 + am] = a4.x;
            as[(ak + 1) * 68 + am] = a4.y;
            as[(ak + 2) * 68 + am] = a4.z;
            as[(ak + 3) * 68 + am] = a4.w;
        }
        CPA_COMMIT();
    }

    for (int t = 0; t < nT; t++) {
        CPA_WAIT1();
        __syncthreads();
        int tf = t + 2;
        int bufF = tf % 3;
        float4 a4 = make_float4(0.f, 0.f, 0.f, 0.f);
        bool fwd = (tf < nT);
        if (fwd) {
            long boff = (long)(tf * 16 + bk) * 256 + n0 + bn;
            #pragma unroll
            for (int s = 0; s < S; s++) {
                uint32_t dst = bsu + (uint32_t)(((((bufF * S + s) * 16 + bk) * 68 + bn)) * 4);
                CPA16(dst, Bp[s] + boff);
            }
            if (m0 + am < M) a4 = *(const float4*)&Ap[(long)(m0 + am) * K + tf * 16 + ak];
        }
        CPA_COMMIT();

        int buf = t % 3;
        const float* as = AsB + buf * 1088;
        #pragma unroll
        for (int kk = 0; kk < 16; kk++) {
            float4 av4 = *(const float4*)&as[kk * 68 + ty * 4];
            float av[4] = {av4.x, av4.y, av4.z, av4.w};
            #pragma unroll
            for (int s = 0; s < S; s++) {
                float4 b4 = *(const float4*)&BsB[((buf * S + s) * 16 + kk) * 68 + tx * 4];
                float bv[4] = {b4.x, b4.y, b4.z, b4.w};
                #pragma unroll
                for (int u = 0; u < 4; u++)
                    #pragma unroll
                    for (int v = 0; v < 4; v++)
                        acc[s][u][v] = fmaf(av[u], bv[v], acc[s][u][v]);
            }
        }
        if (fwd) {
            float* asF = AsB + bufF * 1088;
            asF[(ak + 0) * 68 + am] = a4.x;
            asF[(ak + 1) * 68 + am] = a4.y;
            asF[(ak + 2) * 68 + am] = a4.z;
            asF[(ak + 3) * 68 + am] = a4.w;
        }
    }

    #pragma unroll
    for (int s = 0; s < S; s++) {
        long slab = (long)g * 32 + p + PDIV * s;
        #pragma unroll
        for (int u = 0; u < 4; u++) {
            int m = m0 + ty * 4 + u;
            if (m >= M) continue;
            float bi = bias  ? bias [g * pG + m]       : 0.f;
            float sc = scale ? scale[g * pG + m] * BNS : 1.f;
            float sh = shift ? shift[g * pG + m]       : 0.f;
            float4 o;
            o.x = (acc[s][u][0] + bi) * sc + sh;
            o.y = (acc[s][u][1] + bi) * sc + sh;
            o.z = (acc[s][u][2] + bi) * sc + sh;
            o.w = (acc[s][u][3] + bi) * sc + sh;
            *(float4*)&C[slab * M * 256 + (long)m * 256 + n0 + tx * 4] = o;
        }
    }
}

// ================= LIF kernels =============================================
__global__ void lif4_kernel(float4* __restrict__ buf, long M4)
{
    long tid = (long)blockIdx.x * blockDim.x + threadIdx.x;
    long total = 8 * M4;
    if (tid >= total) return;
    long j = tid % M4;
    int  b = (int)(tid / M4);
    float4 mem = make_float4(0.f, 0.f, 0.f, 0.f);
    #pragma unroll
    for (int t = 0; t < 4; t++) {
        long idx = (long)(t * 8 + b) * M4 + j;
        float4 x = buf[idx];
        float4 sp;
        mem.x += (x.x - mem.x) * 0.5f; sp.x = (mem.x >= 1.f) ? 1.f : 0.f; mem.x *= (1.f - sp.x);
        mem.y += (x.y - mem.y) * 0.5f; sp.y = (mem.y >= 1.f) ? 1.f : 0.f; mem.y *= (1.f - sp.y);
        mem.z += (x.z - mem.z) * 0.5f; sp.z = (mem.z >= 1.f) ? 1.f : 0.f; mem.z *= (1.f - sp.z);
        mem.w += (x.w - mem.w) * 0.5f; sp.w = (mem.w >= 1.f) ? 1.f : 0.f; mem.w *= (1.f - sp.w);
        buf[idx] = sp;
    }
}

__global__ void lif4_add_kernel(const float4* __restrict__ pre, const float4* __restrict__ base,
                                float4* __restrict__ outv, long M4)
{
    long tid = (long)blockIdx.x * blockDim.x + threadIdx.x;
    long total = 8 * M4;
    if (tid >= total) return;
    long j = tid % M4;
    int  b = (int)(tid / M4);
    float4 mem = make_float4(0.f, 0.f, 0.f, 0.f);
    #pragma unroll
    for (int t = 0; t < 4; t++) {
        long idx = (long)(t * 8 + b) * M4 + j;
        float4 x = pre[idx];
        float4 bs = base[idx];
        float4 sp;
        mem.x += (x.x - mem.x) * 0.5f; sp.x = (mem.x >= 1.f) ? 1.f : 0.f; mem.x *= (1.f - sp.x);
        mem.y += (x.y - mem.y) * 0.5f; sp.y = (mem.y >= 1.f) ? 1.f : 0.f; mem.y *= (1.f - sp.y);
        mem.z += (x.z - mem.z) * 0.5f; sp.z = (mem.z >= 1.f) ? 1.f : 0.f; mem.z *= (1.f - sp.z);
        mem.w += (x.w - mem.w) * 0.5f; sp.w = (mem.w >= 1.f) ? 1.f : 0.f; mem.w *= (1.f - sp.w);
        outv[idx] = make_float4(bs.x + sp.x, bs.y + sp.y, bs.z + sp.z, bs.w + sp.w);
    }
}

__global__ void lif_q_kernel()
{
    int tid = blockIdx.x * 256 + threadIdx.x;
    if (tid >= 4*8*96*256) return;
    int n = tid & 255;
    int c = (tid >> 8) % 96;
    int b = (tid / (256*96)) & 7;
    int e = tid / (256*96*8);
    float mem = 0.f;
    #pragma unroll
    for (int t = 0; t < 4; t++) {
        int eb = e*32 + t*8 + b;
        float x = g_q[((long)eb*96 + c)*256 + n];
        mem = mem + (x - mem) * 0.5f;
        unsigned short sp = (mem >= 1.f) ? 0x3F80 : 0;
        mem *= (sp ? 0.f : 1.f);
        g_qb[((long)eb*256 + n)*96 + c] = sp;
    }
}
__global__ void lif_k_kernel()
{
    int tid = blockIdx.x * 256 + threadIdx.x;
    if (tid >= 8*96*256) return;
    int m = tid & 255;
    int c = (tid >> 8) % 96;
    int b = tid / (256*96);
    float mem = 0.f;
    #pragma unroll
    for (int t = 0; t < 4; t++) {
        int tb = t*8 + b;
        float x = g_k[((long)tb*96 + c)*256 + m];
        mem = mem + (x - mem) * 0.5f;
        unsigned short sp = (mem >= 1.f) ? 0x3F80 : 0;
        mem *= (sp ? 0.f : 1.f);
        g_kb[((long)tb*256 + m)*96 + c] = sp;
    }
}
__global__ void lif_v_kernel()
{
    int tid = blockIdx.x * 256 + threadIdx.x;
    if (tid >= 8*384*256) return;
    int m = tid & 255;
    int d = (tid >> 8) % 384;
    int b = tid / (256*384);
    float mem = 0.f;
    #pragma unroll
    for (int t = 0; t < 4; t++) {
        int tb = t*8 + b;
        long idx = ((long)tb*384 + d)*256 + m;
        float x = g_v[idx];
        mem = mem + (x - mem) * 0.5f;
        unsigned short sp = (mem >= 1.f) ? 0x3F80 : 0;
        mem *= (sp ? 0.f : 1.f);
        g_vb[idx] = sp;
    }
}

// ================= attn via mma.sync =======================================
__global__ __launch_bounds__(256) void attn_mma_kernel()
{
    extern __shared__ unsigned short smu[];    // As[128][104], Bs[128][104]
    unsigned short* As = smu;
    unsigned short* Bs = smu + 128*104;
    int mt = blockIdx.x, nt = blockIdx.y, eb = blockIdx.z;
    int tb = eb & 31;
    int tid = threadIdx.x, lane = tid & 31, warp = tid >> 5;

    const uint4* gq = (const uint4*)(g_qb + ((long)eb*256 + nt*128)*96);
    for (int idx = tid; idx < 1536; idx += 256) {
        int i = idx / 12, s = idx % 12;
        *(uint4*)(As + i*104 + s*8) = gq[idx];
    }
    const uint4* gk = (const uint4*)(g_kb + ((long)tb*256 + mt*128)*96);
    for (int idx = tid; idx < 1536; idx += 256) {
        int i = idx / 12, s = idx % 12;
        *(uint4*)(Bs + i*104 + s*8) = gk[idx];
    }
    __syncthreads();

    int wn = (warp >> 2) * 64, wm = (warp & 3) * 32;
    float acc[4][4][4] = {};
    uint32_t base = smem_u32(smu);
    int aRow = lane & 15, aK = (lane >> 4) * 8;
    int bRow = lane & 7,  bK = ((lane >> 3) & 1) * 8;

    #pragma unroll
    for (int kt = 0; kt < 6; kt++) {
        uint32_t a[4][4], bf[4][2];
        #pragma unroll
        for (int r = 0; r < 4; r++) {
            uint32_t ad = base + (uint32_t)(((wn + r*16 + aRow)*104 + kt*16 + aK) * 2);
            LDMX4(a[r][0], a[r][1], a[r][2], a[r][3], ad);
        }
        #pragma unroll
        for (int c = 0; c < 4; c++) {
            uint32_t ad = base + (uint32_t)((128*104 + (wm + c*8 + bRow)*104 + kt*16 + bK) * 2);
            LDMX2(bf[c][0], bf[c][1], ad);
        }
        #pragma unroll
        for (int r = 0; r < 4; r++)
            #pragma unroll
            for (int c = 0; c < 4; c++)
                MMA16816(acc[r][c][0], acc[r][c][1], acc[r][c][2], acc[r][c][3],
                         a[r][0], a[r][1], a[r][2], a[r][3], bf[c][0], bf[c][1]);
    }

    unsigned short* ga = g_ab + (long)eb * 65536;
    #pragma unroll
    for (int r = 0; r < 4; r++) {
        int n = nt*128 + wn + r*16 + (lane >> 2);
        #pragma unroll
        for (int c = 0; c < 4; c++) {
            int m = mt*128 + wm + c*8 + (lane & 3)*2;
            uint32_t p0 = (uint32_t)__bfloat16_as_ushort(__float2bfloat16(acc[r][c][0]))
                        | ((uint32_t)__bfloat16_as_ushort(__float2bfloat16(acc[r][c][1])) << 16);
            uint32_t p1 = (uint32_t)__bfloat16_as_ushort(__float2bfloat16(acc[r][c][2]))
                        | ((uint32_t)__bfloat16_as_ushort(__float2bfloat16(acc[r][c][3])) << 16);
            *(uint32_t*)(ga + (long)n*256 + m)       = p0;
            *(uint32_t*)(ga + (long)(n+8)*256 + m)   = p1;
        }
    }
}

// ================= res via mma.sync ========================================
__global__ __launch_bounds__(256) void res_mma_kernel()
{
    __shared__ unsigned short As[128*72];
    __shared__ unsigned short Bs[128*72];
    int dt = blockIdx.x, nt = blockIdx.y, eb = blockIdx.z;
    int tb = eb & 31;
    int tid = threadIdx.x, lane = tid & 31, warp = tid >> 5;
    int wn = (warp >> 2) * 64, wm = (warp & 3) * 32;
    float acc[4][4][4] = {};
    uint32_t baseA = smem_u32(As), baseB = smem_u32(Bs);
    int aRow = lane & 15, aK = (lane >> 4) * 8;
    int bRow = lane & 7,  bK = ((lane >> 3) & 1) * 8;

    for (int ch = 0; ch < 4; ch++) {
        const uint4* gA = (const uint4*)(g_ab + ((long)eb*256 + nt*128)*256 + ch*64);
        for (int idx = tid; idx < 1024; idx += 256) {
            int i = idx >> 3, s = idx & 7;
            *(uint4*)(As + i*72 + s*8) = gA[i*32 + s];
        }
        const uint4* gB = (const uint4*)(g_vb + ((long)tb*384 + dt*128)*256 + ch*64);
        for (int idx = tid; idx < 1024; idx += 256) {
            int i = idx >> 3, s = idx & 7;
            *(uint4*)(Bs + i*72 + s*8) = gB[i*32 + s];
        }
        __syncthreads();
        #pragma unroll
        for (int kt = 0; kt < 4; kt++) {
            uint32_t a[4][4], bf[4][2];
            #pragma unroll
            for (int r = 0; r < 4; r++) {
                uint32_t ad = baseA + (uint32_t)(((wn + r*16 + aRow)*72 + kt*16 + aK) * 2);
                LDMX4(a[r][0], a[r][1], a[r][2], a[r][3], ad);
            }
            #pragma unroll
            for (int c = 0; c < 4; c++) {
                uint32_t ad = baseB + (uint32_t)(((wm + c*8 + bRow)*72 + kt*16 + bK) * 2);
                LDMX2(bf[c][0], bf[c][1], ad);
            }
            #pragma unroll
            for (int r = 0; r < 4; r++)
                #pragma unroll
                for (int c = 0; c < 4; c++)
                    MMA16816(acc[r][c][0], acc[r][c][1], acc[r][c][2], acc[r][c][3],
                             a[r][0], a[r][1], a[r][2], a[r][3], bf[c][0], bf[c][1]);
        }
        __syncthreads();
    }

    #pragma unroll
    for (int r = 0; r < 4; r++) {
        int n = nt*128 + wn + r*16 + (lane >> 2);
        #pragma unroll
        for (int c = 0; c < 4; c++) {
            int d = dt*128 + wm + c*8 + (lane & 3)*2;
            float2 v0 = make_float2(acc[r][c][0], acc[r][c][1]);
            float2 v1 = make_float2(acc[r][c][2], acc[r][c][3]);
            *(float2*)(g_res + ((long)eb*256 + n)*384 + d)     = v0;
            *(float2*)(g_res + ((long)eb*256 + n + 8)*384 + d) = v1;
        }
    }
}

// ========== exact-fp32 linear via 3-split bf16 mma =========================
__global__ __launch_bounds__(256) void wmma_lin_kernel(
    const unsigned short* __restrict__ A3, const unsigned short* __restrict__ Bb,
    float* __restrict__ outF,
    const float* __restrict__ bias, const float* __restrict__ scale,
    const float* __restrict__ shift, int M, int K)
{
    __shared__ unsigned short As[3*128*40];
    __shared__ unsigned short Bs[128*40];
    int mt = blockIdx.x, nt = blockIdx.y, z = blockIdx.z;
    int tid = threadIdx.x, lane = tid & 31, warp = tid >> 5;
    int m0 = mt * 128;
    int wn = (warp >> 2) * 64, wm = (warp & 3) * 32;
    float acc[4][4][4] = {};
    uint32_t baseA = smem_u32(As), baseB = smem_u32(Bs);
    int aRow = lane & 15, aK = (lane >> 4) * 8;
    int bRow = lane & 7,  bK = ((lane >> 3) & 1) * 8;

    for (int k0 = 0; k0 < K; k0 += 32) {
        for (int idx = tid; idx < 1536; idx += 256) {
            int s = idx / 512, r = idx % 512;
            int i = r >> 2, p4 = r & 3;
            *(uint4*)(As + (s*128 + i)*40 + p4*8) =
                *(const uint4*)(A3 + ((long)s*M + m0 + i)*K + k0 + p4*8);
        }
        for (int idx = tid; idx < 512; idx += 256) {
            int i = idx >> 2, p4 = idx & 3;
            *(uint4*)(Bs + i*40 + p4*8) =
                *(const uint4*)(Bb + ((long)z*256 + nt*128 + i)*K + k0 + p4*8);
        }
        __syncthreads();
        #pragma unroll
        for (int kt = 0; kt < 2; kt++) {
            uint32_t bf[4][2];
            #pragma unroll
            for (int c = 0; c < 4; c++) {
                uint32_t ad = baseB + (uint32_t)(((wm + c*8 + bRow)*40 + kt*16 + bK) * 2);
                LDMX2(bf[c][0], bf[c][1], ad);
            }
            #pragma unroll
            for (int s = 0; s < 3; s++) {
                uint32_t a[4][4];
                #pragma unroll
                for (int r = 0; r < 4; r++) {
                    uint32_t ad = baseA + (uint32_t)(((s*128 + wn + r*16 + aRow)*40 + kt*16 + aK) * 2);
                    LDMX4(a[r][0], a[r][1], a[r][2], a[r][3], ad);
                }
                #pragma unroll
                for (int r = 0; r < 4; r++)
                    #pragma unroll
                    for (int c = 0; c < 4; c++)
                        MMA16816(acc[r][c][0], acc[r][c][1], acc[r][c][2], acc[r][c][3],
                                 a[r][0], a[r][1], a[r][2], a[r][3], bf[c][0], bf[c][1]);
            }
        }
        __syncthreads();
    }

    #pragma unroll
    for (int r = 0; r < 4; r++) {
        int m  = m0 + wn + r*16 + (lane >> 2);
        float bi0 = bias[m],   sc0 = scale[m]   * BNS, sh0 = shift[m];
        float bi1 = bias[m+8], sc1 = scale[m+8] * BNS, sh1 = shift[m+8];
        #pragma unroll
        for (int c = 0; c < 4; c++) {
            int n = nt*128 + wm + c*8 + (lane & 3)*2;
            float2 v0, v1;
            v0.x = (acc[r][c][0] + bi0) * sc0 + sh0;
            v0.y = (acc[r][c][1] + bi0) * sc0 + sh0;
            v1.x = (acc[r][c][2] + bi1) * sc1 + sh1;
            v1.y = (acc[r][c][3] + bi1) * sc1 + sh1;
            *(float2*)(outF + ((long)z*M + m)*256 + n)     = v0;
            *(float2*)(outF + ((long)z*M + m + 8)*256 + n) = v1;
        }
    }
}

// ================= helper kernels ==========================================
__global__ void wsplit3_kernel(const float* __restrict__ w, unsigned short* __restrict__ w3, int total)
{
    int i = blockIdx.x * 256 + threadIdx.x;
    if (i >= total) return;
    float x = w[i];
    __nv_bfloat16 h0 = __float2bfloat16(x);
    float r1 = x - __bfloat162float(h0);
    __nv_bfloat16 h1 = __float2bfloat16(r1);
    float r2 = r1 - __bfloat162float(h1);
    __nv_bfloat16 h2 = __float2bfloat16(r2);
    w3[i]             = __bfloat16_as_ushort(h0);
    w3[total + i]     = __bfloat16_as_ushort(h1);
    w3[2 * total + i] = __bfloat16_as_ushort(h2);
}

__global__ void combine_lif_kernel()
{
    long tid = (long)blockIdx.x * 256 + threadIdx.x;
    if (tid >= (long)8 * 256 * 384) return;
    int d = (int)(tid % 384);
    int n = (int)((tid / 384) % 256);
    int b = (int)(tid / (384 * 256));
    float y[4] = {0.f, 0.f, 0.f, 0.f};
    #pragma unroll
    for (int e = 0; e < 4; e++) {
        float mem = 0.f;
        #pragma unroll
        for (int t = 0; t < 4; t++) {
            int eb = e * 32 + t * 8 + b;
            float pre = g_res[((long)eb * 256 + n) * 384 + d];
            mem = mem + (pre - mem) * 0.5f;
            float sp = (mem >= 1.f) ? 1.f : 0.f;
            mem *= (1.f - sp);
            y[t] = fmaf(g_w[((t * 8 + b) * 4 + e) * 256 + n], sp, y[t]);
        }
    }
    #pragma unroll
    for (int t = 0; t < 4; t++)
        g_yb[((long)(t * 8 + b) * 256 + n) * 384 + d] =
            __bfloat16_as_ushort(__float2bfloat16(y[t]));
}

__global__ void transpose_m_kernel()
{
    __shared__ unsigned short tile[32][33];
    int c0 = blockIdx.x * 32, n0 = blockIdx.y * 32, tb = blockIdx.z;
    int tx = threadIdx.x & 31, ty = threadIdx.x >> 5;
    #pragma unroll
    for (int p = 0; p < 4; p++) {
        int c = c0 + ty + p*8;
        tile[ty + p*8][tx] = __bfloat16_as_ushort(
            __float2bfloat16(g_m[((long)tb*1024 + c)*256 + n0 + tx]));
    }
    __syncthreads();
    #pragma unroll
    for (int p = 0; p < 4; p++) {
        int n = n0 + ty + p*8;
        g_mb[((long)tb*256 + n)*1024 + c0 + tx] = tile[tx][ty + p*8];
    }
}

__global__ void dwconv_gate_kernel(const float* __restrict__ dw_w, const float* __restrict__ dw_b,
                                   const float* __restrict__ dw_g, const float* __restrict__ dw_be)
{
    int tid = blockIdx.x * 256 + threadIdx.x;
    if (tid >= 8 * 1024 * 256) return;
    int n  = tid & 255;
    int c  = (tid >> 8) & 1023;
    int b  = tid >> 18;
    int hh = n >> 4, ww = n & 15;
    float wk[9];
    #pragma unroll
    for (int i = 0; i < 9; i++) wk[i] = dw_w[c * 9 + i];
    float bi = dw_b[c], sc = dw_g[c] * BNS, sh = dw_be[c];
    float mem = 0.f;
    #pragma unroll
    for (int t = 0; t < 4; t++) {
        int tb = t * 8 + b;
        const float* x1 = g_h + ((long)tb * 2048 + c) * 256;
        float acc = bi;
        #pragma unroll
        for (int di = 0; di < 3; di++) {
            int yy = hh + di - 1;
            if (yy < 0 || yy > 15) continue;
            #pragma unroll
            for (int dj = 0; dj < 3; dj++) {
                int xx = ww + dj - 1;
                if (xx < 0 || xx > 15) continue;
                acc = fmaf(wk[di * 3 + dj], x1[yy * 16 + xx], acc);
            }
        }
        float pre = acc * sc + sh;
        mem = mem + (pre - mem) * 0.5f;
        float sp = (mem >= 1.f) ? 1.f : 0.f;
        mem *= (1.f - sp);
        float x2 = g_h[((long)tb * 2048 + 1024 + c) * 256 + n];
        g_m[((long)tb * 1024 + c) * 256 + n] = sp * x2;
    }
}

// ===========================================================================
extern "C" void kernel_launch(void* const* d_in, const int* in_sizes, int n_in,
                              void* d_out, int out_size)
{
    const float* x         = (const float*)d_in[0];
    const float* k_w       = (const float*)d_in[2];
    const float* v_w       = (const float*)d_in[3];
    const float* router_w  = (const float*)d_in[4];
    const float* router_b  = (const float*)d_in[5];
    const float* router_g  = (const float*)d_in[6];
    const float* router_be = (const float*)d_in[7];
    const float* exp_w     = (const float*)d_in[8];
    const float* exp_g     = (const float*)d_in[9];
    const float* exp_b     = (const float*)d_in[10];
    const float* proj_w    = (const float*)d_in[11];
    const float* proj_b    = (const float*)d_in[12];
    const float* proj_g    = (const float*)d_in[13];
    const float* proj_be   = (const float*)d_in[14];
    const float* fc1_w     = (const float*)d_in[15];
    const float* fc1_b     = (const float*)d_in[16];
    const float* fc1_g     = (const float*)d_in[17];
    const float* fc1_be    = (const float*)d_in[18];
    const float* dw_w      = (const float*)d_in[19];
    const float* dw_b      = (const float*)d_in[20];
    const float* dw_g      = (const float*)d_in[21];
    const float* dw_be     = (const float*)d_in[22];
    const float* fc2_w     = (const float*)d_in[23];
    const float* fc2_b     = (const float*)d_in[24];
    const float* fc2_g     = (const float*)d_in[25];
    const float* fc2_be    = (const float*)d_in[26];
    float* out = (float*)d_out;

    float *pk, *pv, *pw, *pq, *pp, *pxr, *ph, *pm, *pf2, *pres;
    unsigned short *pqb, *pkb, *pvb, *pyb, *pmb, *pw3a, *pw3b;
    cudaGetSymbolAddress((void**)&pk,   g_k);
    cudaGetSymbolAddress((void**)&pv,   g_v);
    cudaGetSymbolAddress((void**)&pw,   g_w);
    cudaGetSymbolAddress((void**)&pq,   g_q);
    cudaGetSymbolAddress((void**)&pres, g_res);
    cudaGetSymbolAddress((void**)&pp,   g_p);
    cudaGetSymbolAddress((void**)&pxr,  g_xr);
    cudaGetSymbolAddress((void**)&ph,   g_h);
    cudaGetSymbolAddress((void**)&pm,   g_m);
    cudaGetSymbolAddress((void**)&pf2,  g_f2);
    cudaGetSymbolAddress((void**)&pqb,  g_qb);
    cudaGetSymbolAddress((void**)&pkb,  g_kb);
    cudaGetSymbolAddress((void**)&pvb,  g_vb);
    cudaGetSymbolAddress((void**)&pyb,  g_yb);
    cudaGetSymbolAddress((void**)&pmb,  g_mb);
    cudaGetSymbolAddress((void**)&pw3a, g_w3a);
    cudaGetSymbolAddress((void**)&pw3b, g_w3b);

    cudaFuncSetAttribute(attn_mma_kernel, cudaFuncAttributeMaxDynamicSharedMemorySize, 53248);
    cudaFuncSetAttribute(gemm_zs_kernel<2>, cudaFuncAttributeMaxDynamicSharedMemorySize, 39168);
    cudaFuncSetAttribute(gemm_zs_kernel<4>, cudaFuncAttributeMaxDynamicSharedMemorySize, 65280);

    const long XB = 384 * 256;
    dim3 blk(256);
    const int SM2 = 39168, SM4 = 65280;

    // weight splits
    wsplit3_kernel<<<(384*384+255)/256,blk>>>(proj_w, pw3a, 384*384);
    wsplit3_kernel<<<(384*1024+255)/256,blk>>>(fc2_w, pw3b, 384*1024);

    // --- SSA pre-activations (cp.async pipelined z-share GEMMs) ---
    gemm_zs_kernel<2><<<dim3(4,2,16),blk,SM2>>>(k_w,0, x,XB,
        pk, nullptr,nullptr,nullptr,0, 96,384);
    gemm_zs_kernel<2><<<dim3(4,6,16),blk,SM2>>>(v_w,0, x,XB,
        pv, nullptr,nullptr,nullptr,0, 384,384);
    gemm_zs_kernel<2><<<dim3(4,1,16),blk,SM2>>>(router_w,0, x,XB,
        pw, router_b,router_g,router_be,0, 4,384);
    gemm_zs_kernel<4><<<dim3(4,2,32),blk,SM4>>>(exp_w,(long)96*384, x,XB,
        pq, nullptr,exp_g,exp_b,96, 96,384);

    // --- LIF -> bf16 spikes in mma layouts ---
    lif_k_kernel<<<(8*96*256+255)/256,blk>>>();
    lif_v_kernel<<<(8*384*256+255)/256,blk>>>();
    lif4_kernel<<<(8*256+255)/256,blk>>>((float4*)pw, 256);
    lif_q_kernel<<<(4*8*96*256+255)/256,blk>>>();

    // --- tensor-core attention ---
    attn_mma_kernel<<<dim3(2,2,128),blk,53248>>>();
    res_mma_kernel<<<dim3(3,2,128),blk>>>();

    // fused res-LIF + combine -> bf16 y
    combine_lif_kernel<<<(8*256*384+255)/256,blk>>>();

    // proj on tensor cores -> pre-acts; fused LIF+residual: xr = x + spike(p)
    wmma_lin_kernel<<<dim3(3,2,32),blk>>>(pw3a, pyb, pp, proj_b, proj_g, proj_be, 384, 384);
    lif4_add_kernel<<<(8*24576+255)/256,blk>>>((const float4*)pp, (const float4*)x,
                                               (float4*)pxr, 24576);

    // --- MLP ---
    gemm_zs_kernel<4><<<dim3(4,32,8),blk,SM4>>>(fc1_w,0, pxr,XB,
        ph, fc1_b,fc1_g,fc1_be,0, 2048,384);
    lif4_kernel<<<(8*131072+255)/256,blk>>>((float4*)ph, 131072);
    dwconv_gate_kernel<<<(8*1024*256+255)/256,blk>>>(dw_w, dw_b, dw_g, dw_be);
    transpose_m_kernel<<<dim3(32,8,32),blk>>>();

    // fc2 on tensor cores -> pre-acts; fused LIF+residual: out = xr + spike(f2)
    wmma_lin_kernel<<<dim3(3,2,32),blk>>>(pw3b, pmb, pf2, fc2_b, fc2_g, fc2_be, 384, 1024);
    lif4_add_kernel<<<(8*24576+255)/256,blk>>>((const float4*)pf2, (const float4*)pxr,
                                               (float4*)out, 24576);
}

// round 13
// speedup vs baseline: 1.0727x; 1.0727x over previous
#include <cuda_runtime.h>
#include <cuda_bf16.h>
#include <cstdint>
#include <math.h>

#define BNS 0.9999950000374996f  // 1/sqrt(1+1e-5)

// ================= scratch (device globals) ================================
__device__ float g_k   [32*96*256];
__device__ float g_v   [32*384*256];
__device__ float g_w   [32*4*256];
__device__ float g_res [4*32*256*384];     // res PRE-acts (E*TB,N,C)
__device__ float g_p   [32*384*256];       // proj PRE-acts
__device__ float g_xr  [32*384*256];
__device__ float g_h   [32*2048*256];      // fc1 SPIKES (fused)
__device__ float g_m   [32*1024*256];
__device__ float g_f2  [32*384*256];       // fc2 PRE-acts
__device__ unsigned short g_qb[128*256*96];
__device__ unsigned short g_kb[32*256*96];
__device__ unsigned short g_vb[32*384*256];
__device__ unsigned short g_ab[128*256*256];
__device__ unsigned short g_yb[32*256*384];
__device__ unsigned short g_mb[32*256*1024];
__device__ unsigned short g_w3a[3*384*384];
__device__ unsigned short g_w3b[3*384*1024];

__device__ __forceinline__ uint32_t smem_u32(const void* p){
    uint32_t a;
    asm("{ .reg .u64 t; cvta.to.shared.u64 t, %1; cvt.u32.u64 %0, t; }" : "=r"(a) : "l"(p));
    return a;
}
#define LDMX4(r0,r1,r2,r3,ad) \
    asm volatile("ldmatrix.sync.aligned.m8n8.x4.shared.b16 {%0,%1,%2,%3}, [%4];" \
        : "=r"(r0),"=r"(r1),"=r"(r2),"=r"(r3) : "r"(ad))
#define LDMX2(r0,r1,ad) \
    asm volatile("ldmatrix.sync.aligned.m8n8.x2.shared.b16 {%0,%1}, [%2];" \
        : "=r"(r0),"=r"(r1) : "r"(ad))
#define MMA16816(c0,c1,c2,c3,a0,a1,a2,a3,b0,b1) \
    asm volatile("mma.sync.aligned.m16n8k16.row.col.f32.bf16.bf16.f32 " \
        "{%0,%1,%2,%3}, {%4,%5,%6,%7}, {%8,%9}, {%0,%1,%2,%3};" \
        : "+f"(c0),"+f"(c1),"+f"(c2),"+f"(c3) \
        : "r"(a0),"r"(a1),"r"(a2),"r"(a3),"r"(b0),"r"(b1))
#define CPA16(dst, src) \
    asm volatile("cp.async.cg.shared.global [%0], [%1], 16;" :: "r"(dst), "l"(src) : "memory")
#define CPA_COMMIT() asm volatile("cp.async.commit_group;" ::: "memory")
#define CPA_WAIT1()  asm volatile("cp.async.wait_group 1;"  ::: "memory")

// ===== SIMT GEMM, S z-slabs share one A tile, cp.async 3-stage pipeline ====
template<int S>
__global__ __launch_bounds__(256) void gemm_zs_kernel(
    const float* __restrict__ A, long aG,
    const float* __restrict__ B, long bSlab,
    float* __restrict__ C,
    const float* __restrict__ bias, const float* __restrict__ scale,
    const float* __restrict__ shift, int pG,
    int M, int K)
{
    extern __shared__ float sm[];
    float* AsB = sm;               // [3][16][68]
    float* BsB = sm + 3 * 1088;    // [3][S][16][68]
    const int PDIV = 32 / S;
    int bz = blockIdx.z;
    int g = bz / PDIV, p = bz % PDIV;
    const float* Ap = A + (long)g * aG;
    const float* Bp[S];
    #pragma unroll
    for (int s = 0; s < S; s++) Bp[s] = B + (long)(p + PDIV * s) * bSlab;
    int m0 = blockIdx.y * 64, n0 = blockIdx.x * 64;
    int tid = threadIdx.x, tx = tid & 15, ty = tid >> 4;
    int am = tid >> 2, ak = (tid & 3) * 4;
    int bk = tid >> 4, bn = (tid & 15) * 4;
    uint32_t bsu = smem_u32(BsB);
    float acc[S][4][4] = {};
    int nT = K >> 4;

    #pragma unroll
    for (int st = 0; st < 2; st++) {
        if (st < nT) {
            long boff = (long)(st * 16 + bk) * 256 + n0 + bn;
            #pragma unroll
            for (int s = 0; s < S; s++) {
                uint32_t dst = bsu + (uint32_t)(((((st * S + s) * 16 + bk) * 68 + bn)) * 4);
                CPA16(dst, Bp[s] + boff);
            }
            float4 a4 = make_float4(0.f, 0.f, 0.f, 0.f);
            if (m0 + am < M) a4 = *(const float4*)&Ap[(long)(m0 + am) * K + st * 16 + ak];
            float* as = AsB + st * 1088;
            as[(ak + 0) * 68 + am] = a4.x;
            as[(ak + 1) * 68 + am] = a4.y;
            as[(ak + 2) * 68 + am] = a4.z;
            as[(ak + 3) * 68 + am] = a4.w;
        }
        CPA_COMMIT();
    }

    for (int t = 0; t < nT; t++) {
        CPA_WAIT1();
        __syncthreads();
        int tf = t + 2;
        int bufF = tf % 3;
        float4 a4 = make_float4(0.f, 0.f, 0.f, 0.f);
        bool fwd = (tf < nT);
        if (fwd) {
            long boff = (long)(tf * 16 + bk) * 256 + n0 + bn;
            #pragma unroll
            for (int s = 0; s < S; s++) {
                uint32_t dst = bsu + (uint32_t)(((((bufF * S + s) * 16 + bk) * 68 + bn)) * 4);
                CPA16(dst, Bp[s] + boff);
            }
            if (m0 + am < M) a4 = *(const float4*)&Ap[(long)(m0 + am) * K + tf * 16 + ak];
        }
        CPA_COMMIT();

        int buf = t % 3;
        const float* as = AsB + buf * 1088;
        #pragma unroll
        for (int kk = 0; kk < 16; kk++) {
            float4 av4 = *(const float4*)&as[kk * 68 + ty * 4];
            float av[4] = {av4.x, av4.y, av4.z, av4.w};
            #pragma unroll
            for (int s = 0; s < S; s++) {
                float4 b4 = *(const float4*)&BsB[((buf * S + s) * 16 + kk) * 68 + tx * 4];
                float bv[4] = {b4.x, b4.y, b4.z, b4.w};
                #pragma unroll
                for (int u = 0; u < 4; u++)
                    #pragma unroll
                    for (int v = 0; v < 4; v++)
                        acc[s][u][v] = fmaf(av[u], bv[v], acc[s][u][v]);
            }
        }
        if (fwd) {
            float* asF = AsB + bufF * 1088;
            asF[(ak + 0) * 68 + am] = a4.x;
            asF[(ak + 1) * 68 + am] = a4.y;
            asF[(ak + 2) * 68 + am] = a4.z;
            asF[(ak + 3) * 68 + am] = a4.w;
        }
    }

    #pragma unroll
    for (int s = 0; s < S; s++) {
        long slab = (long)g * 32 + p + PDIV * s;
        #pragma unroll
        for (int u = 0; u < 4; u++) {
            int m = m0 + ty * 4 + u;
            if (m >= M) continue;
            float bi = bias  ? bias [g * pG + m]       : 0.f;
            float sc = scale ? scale[g * pG + m] * BNS : 1.f;
            float sh = shift ? shift[g * pG + m]       : 0.f;
            float4 o;
            o.x = (acc[s][u][0] + bi) * sc + sh;
            o.y = (acc[s][u][1] + bi) * sc + sh;
            o.z = (acc[s][u][2] + bi) * sc + sh;
            o.w = (acc[s][u][3] + bi) * sc + sh;
            *(float4*)&C[slab * M * 256 + (long)m * 256 + n0 + tx * 4] = o;
        }
    }
}

// ===== z4 GEMM + fused 4-step LIF epilogue (slabs p+8s = 4 time steps) =====
// MODE 1: fp32 spikes row-major -> outF[slab*M*256 + m*256 + n]
// MODE 2: bf16 spikes n-major   -> outB[(slab*256 + n)*M + m]
template<int MODE>
__global__ __launch_bounds__(256) void gemm_z4lif_kernel(
    const float* __restrict__ A, long aG,
    const float* __restrict__ B, long bSlab,
    float* __restrict__ outF, unsigned short* __restrict__ outB,
    const float* __restrict__ bias, const float* __restrict__ scale,
    const float* __restrict__ shift, int pG,
    int M, int K)
{
    extern __shared__ float sm[];
    float* AsB = sm;
    float* BsB = sm + 3 * 1088;    // [3][4][16][68]
    int bz = blockIdx.z;
    int g = bz >> 3, p = bz & 7;
    const float* Ap = A + (long)g * aG;
    const float* Bp[4];
    #pragma unroll
    for (int s = 0; s < 4; s++) Bp[s] = B + (long)(p + 8 * s) * bSlab;
    int m0 = blockIdx.y * 64, n0 = blockIdx.x * 64;
    int tid = threadIdx.x, tx = tid & 15, ty = tid >> 4;
    int am = tid >> 2, ak = (tid & 3) * 4;
    int bk = tid >> 4, bn = (tid & 15) * 4;
    uint32_t bsu = smem_u32(BsB);
    float acc[4][4][4] = {};
    int nT = K >> 4;

    #pragma unroll
    for (int st = 0; st < 2; st++) {
        if (st < nT) {
            long boff = (long)(st * 16 + bk) * 256 + n0 + bn;
            #pragma unroll
            for (int s = 0; s < 4; s++) {
                uint32_t dst = bsu + (uint32_t)(((((st * 4 + s) * 16 + bk) * 68 + bn)) * 4);
                CPA16(dst, Bp[s] + boff);
            }
            float4 a4 = make_float4(0.f, 0.f, 0.f, 0.f);
            if (m0 + am < M) a4 = *(const float4*)&Ap[(long)(m0 + am) * K + st * 16 + ak];
            float* as = AsB + st * 1088;
            as[(ak + 0) * 68 + am] = a4.x;
            as[(ak + 1) * 68 + am] = a4.y;
            as[(ak + 2) * 68 + am] = a4.z;
            as[(ak + 3) * 68 + am] = a4.w;
        }
        CPA_COMMIT();
    }

    for (int t = 0; t < nT; t++) {
        CPA_WAIT1();
        __syncthreads();
        int tf = t + 2;
        int bufF = tf % 3;
        float4 a4 = make_float4(0.f, 0.f, 0.f, 0.f);
        bool fwd = (tf < nT);
        if (fwd) {
            long boff = (long)(tf * 16 + bk) * 256 + n0 + bn;
            #pragma unroll
            for (int s = 0; s < 4; s++) {
                uint32_t dst = bsu + (uint32_t)(((((bufF * 4 + s) * 16 + bk) * 68 + bn)) * 4);
                CPA16(dst, Bp[s] + boff);
            }
            if (m0 + am < M) a4 = *(const float4*)&Ap[(long)(m0 + am) * K + tf * 16 + ak];
        }
        CPA_COMMIT();

        int buf = t % 3;
        const float* as = AsB + buf * 1088;
        #pragma unroll
        for (int kk = 0; kk < 16; kk++) {
            float4 av4 = *(const float4*)&as[kk * 68 + ty * 4];
            float av[4] = {av4.x, av4.y, av4.z, av4.w};
            #pragma unroll
            for (int s = 0; s < 4; s++) {
                float4 b4 = *(const float4*)&BsB[((buf * 4 + s) * 16 + kk) * 68 + tx * 4];
                float bv[4] = {b4.x, b4.y, b4.z, b4.w};
                #pragma unroll
                for (int u = 0; u < 4; u++)
                    #pragma unroll
                    for (int v = 0; v < 4; v++)
                        acc[s][u][v] = fmaf(av[u], bv[v], acc[s][u][v]);
            }
        }
        if (fwd) {
            float* asF = AsB + bufF * 1088;
            asF[(ak + 0) * 68 + am] = a4.x;
            asF[(ak + 1) * 68 + am] = a4.y;
            asF[(ak + 2) * 68 + am] = a4.z;
            asF[(ak + 3) * 68 + am] = a4.w;
        }
    }

    // ---- fused affine + 4-step LIF in registers (acc[s] = time step s) ----
    #pragma unroll
    for (int u = 0; u < 4; u++) {
        int m = m0 + ty * 4 + u;
        bool valid = (m < M);
        float bi = (valid && bias)  ? bias [g * pG + m]       : 0.f;
        float sc = (valid && scale) ? scale[g * pG + m] * BNS : 1.f;
        float sh = (valid && shift) ? shift[g * pG + m]       : 0.f;
        #pragma unroll
        for (int v = 0; v < 4; v++) {
            float mem = 0.f;
            #pragma unroll
            for (int t = 0; t < 4; t++) {
                float pre = (acc[t][u][v] + bi) * sc + sh;
                mem = mem + (pre - mem) * 0.5f;
                float sp = (mem >= 1.f) ? 1.f : 0.f;
                mem *= (1.f - sp);
                acc[t][u][v] = sp;
            }
        }
    }

    if (MODE == 1) {
        #pragma unroll
        for (int t = 0; t < 4; t++) {
            long slab = (long)g * 32 + p + 8 * t;
            #pragma unroll
            for (int u = 0; u < 4; u++) {
                int m = m0 + ty * 4 + u;
                if (m >= M) continue;
                float4 o = make_float4(acc[t][u][0], acc[t][u][1], acc[t][u][2], acc[t][u][3]);
                *(float4*)&outF[slab * M * 256 + (long)m * 256 + n0 + tx * 4] = o;
            }
        }
    } else {
        if (m0 + ty * 4 + 3 < M) {
            #pragma unroll
            for (int t = 0; t < 4; t++) {
                long slab = (long)g * 32 + p + 8 * t;
                #pragma unroll
                for (int v = 0; v < 4; v++) {
                    int n = n0 + tx * 4 + v;
                    ushort4 o;
                    o.x = acc[t][0][v] != 0.f ? 0x3F80 : 0;
                    o.y = acc[t][1][v] != 0.f ? 0x3F80 : 0;
                    o.z = acc[t][2][v] != 0.f ? 0x3F80 : 0;
                    o.w = acc[t][3][v] != 0.f ? 0x3F80 : 0;
                    *(ushort4*)&outB[(slab * 256 + n) * M + m0 + ty * 4] = o;
                }
            }
        }
    }
}

// ================= LIF kernels =============================================
__global__ void lif4_kernel(float4* __restrict__ buf, long M4)
{
    long tid = (long)blockIdx.x * blockDim.x + threadIdx.x;
    long total = 8 * M4;
    if (tid >= total) return;
    long j = tid % M4;
    int  b = (int)(tid / M4);
    float4 mem = make_float4(0.f, 0.f, 0.f, 0.f);
    #pragma unroll
    for (int t = 0; t < 4; t++) {
        long idx = (long)(t * 8 + b) * M4 + j;
        float4 x = buf[idx];
        float4 sp;
        mem.x += (x.x - mem.x) * 0.5f; sp.x = (mem.x >= 1.f) ? 1.f : 0.f; mem.x *= (1.f - sp.x);
        mem.y += (x.y - mem.y) * 0.5f; sp.y = (mem.y >= 1.f) ? 1.f : 0.f; mem.y *= (1.f - sp.y);
        mem.z += (x.z - mem.z) * 0.5f; sp.z = (mem.z >= 1.f) ? 1.f : 0.f; mem.z *= (1.f - sp.z);
        mem.w += (x.w - mem.w) * 0.5f; sp.w = (mem.w >= 1.f) ? 1.f : 0.f; mem.w *= (1.f - sp.w);
        buf[idx] = sp;
    }
}

__global__ void lif4_add_kernel(const float4* __restrict__ pre, const float4* __restrict__ base,
                                float4* __restrict__ outv, long M4)
{
    long tid = (long)blockIdx.x * blockDim.x + threadIdx.x;
    long total = 8 * M4;
    if (tid >= total) return;
    long j = tid % M4;
    int  b = (int)(tid / M4);
    float4 mem = make_float4(0.f, 0.f, 0.f, 0.f);
    #pragma unroll
    for (int t = 0; t < 4; t++) {
        long idx = (long)(t * 8 + b) * M4 + j;
        float4 x = pre[idx];
        float4 bs = base[idx];
        float4 sp;
        mem.x += (x.x - mem.x) * 0.5f; sp.x = (mem.x >= 1.f) ? 1.f : 0.f; mem.x *= (1.f - sp.x);
        mem.y += (x.y - mem.y) * 0.5f; sp.y = (mem.y >= 1.f) ? 1.f : 0.f; mem.y *= (1.f - sp.y);
        mem.z += (x.z - mem.z) * 0.5f; sp.z = (mem.z >= 1.f) ? 1.f : 0.f; mem.z *= (1.f - sp.z);
        mem.w += (x.w - mem.w) * 0.5f; sp.w = (mem.w >= 1.f) ? 1.f : 0.f; mem.w *= (1.f - sp.w);
        outv[idx] = make_float4(bs.x + sp.x, bs.y + sp.y, bs.z + sp.z, bs.w + sp.w);
    }
}

__global__ void lif_k_kernel()
{
    int tid = blockIdx.x * 256 + threadIdx.x;
    if (tid >= 8*96*256) return;
    int m = tid & 255;
    int c = (tid >> 8) % 96;
    int b = tid / (256*96);
    float mem = 0.f;
    #pragma unroll
    for (int t = 0; t < 4; t++) {
        int tb = t*8 + b;
        float x = g_k[((long)tb*96 + c)*256 + m];
        mem = mem + (x - mem) * 0.5f;
        unsigned short sp = (mem >= 1.f) ? 0x3F80 : 0;
        mem *= (sp ? 0.f : 1.f);
        g_kb[((long)tb*256 + m)*96 + c] = sp;
    }
}
__global__ void lif_v_kernel()
{
    int tid = blockIdx.x * 256 + threadIdx.x;
    if (tid >= 8*384*256) return;
    int m = tid & 255;
    int d = (tid >> 8) % 384;
    int b = tid / (256*384);
    float mem = 0.f;
    #pragma unroll
    for (int t = 0; t < 4; t++) {
        int tb = t*8 + b;
        long idx = ((long)tb*384 + d)*256 + m;
        float x = g_v[idx];
        mem = mem + (x - mem) * 0.5f;
        unsigned short sp = (mem >= 1.f) ? 0x3F80 : 0;
        mem *= (sp ? 0.f : 1.f);
        g_vb[idx] = sp;
    }
}

// ================= attn via mma.sync =======================================
__global__ __launch_bounds__(256) void attn_mma_kernel()
{
    extern __shared__ unsigned short smu[];    // As[128][104], Bs[128][104]
    unsigned short* As = smu;
    unsigned short* Bs = smu + 128*104;
    int mt = blockIdx.x, nt = blockIdx.y, eb = blockIdx.z;
    int tb = eb & 31;
    int tid = threadIdx.x, lane = tid & 31, warp = tid >> 5;

    const uint4* gq = (const uint4*)(g_qb + ((long)eb*256 + nt*128)*96);
    for (int idx = tid; idx < 1536; idx += 256) {
        int i = idx / 12, s = idx % 12;
        *(uint4*)(As + i*104 + s*8) = gq[idx];
    }
    const uint4* gk = (const uint4*)(g_kb + ((long)tb*256 + mt*128)*96);
    for (int idx = tid; idx < 1536; idx += 256) {
        int i = idx / 12, s = idx % 12;
        *(uint4*)(Bs + i*104 + s*8) = gk[idx];
    }
    __syncthreads();

    int wn = (warp >> 2) * 64, wm = (warp & 3) * 32;
    float acc[4][4][4] = {};
    uint32_t base = smem_u32(smu);
    int aRow = lane & 15, aK = (lane >> 4) * 8;
    int bRow = lane & 7,  bK = ((lane >> 3) & 1) * 8;

    #pragma unroll
    for (int kt = 0; kt < 6; kt++) {
        uint32_t a[4][4], bf[4][2];
        #pragma unroll
        for (int r = 0; r < 4; r++) {
            uint32_t ad = base + (uint32_t)(((wn + r*16 + aRow)*104 + kt*16 + aK) * 2);
            LDMX4(a[r][0], a[r][1], a[r][2], a[r][3], ad);
        }
        #pragma unroll
        for (int c = 0; c < 4; c++) {
            uint32_t ad = base + (uint32_t)((128*104 + (wm + c*8 + bRow)*104 + kt*16 + bK) * 2);
            LDMX2(bf[c][0], bf[c][1], ad);
        }
        #pragma unroll
        for (int r = 0; r < 4; r++)
            #pragma unroll
            for (int c = 0; c < 4; c++)
                MMA16816(acc[r][c][0], acc[r][c][1], acc[r][c][2], acc[r][c][3],
                         a[r][0], a[r][1], a[r][2], a[r][3], bf[c][0], bf[c][1]);
    }

    unsigned short* ga = g_ab + (long)eb * 65536;
    #pragma unroll
    for (int r = 0; r < 4; r++) {
        int n = nt*128 + wn + r*16 + (lane >> 2);
        #pragma unroll
        for (int c = 0; c < 4; c++) {
            int m = mt*128 + wm + c*8 + (lane & 3)*2;
            uint32_t p0 = (uint32_t)__bfloat16_as_ushort(__float2bfloat16(acc[r][c][0]))
                        | ((uint32_t)__bfloat16_as_ushort(__float2bfloat16(acc[r][c][1])) << 16);
            uint32_t p1 = (uint32_t)__bfloat16_as_ushort(__float2bfloat16(acc[r][c][2]))
                        | ((uint32_t)__bfloat16_as_ushort(__float2bfloat16(acc[r][c][3])) << 16);
            *(uint32_t*)(ga + (long)n*256 + m)       = p0;
            *(uint32_t*)(ga + (long)(n+8)*256 + m)   = p1;
        }
    }
}

// ================= res via mma.sync ========================================
__global__ __launch_bounds__(256) void res_mma_kernel()
{
    __shared__ unsigned short As[128*72];
    __shared__ unsigned short Bs[128*72];
    int dt = blockIdx.x, nt = blockIdx.y, eb = blockIdx.z;
    int tb = eb & 31;
    int tid = threadIdx.x, lane = tid & 31, warp = tid >> 5;
    int wn = (warp >> 2) * 64, wm = (warp & 3) * 32;
    float acc[4][4][4] = {};
    uint32_t baseA = smem_u32(As), baseB = smem_u32(Bs);
    int aRow = lane & 15, aK = (lane >> 4) * 8;
    int bRow = lane & 7,  bK = ((lane >> 3) & 1) * 8;

    for (int ch = 0; ch < 4; ch++) {
        const uint4* gA = (const uint4*)(g_ab + ((long)eb*256 + nt*128)*256 + ch*64);
        for (int idx = tid; idx < 1024; idx += 256) {
            int i = idx >> 3, s = idx & 7;
            *(uint4*)(As + i*72 + s*8) = gA[i*32 + s];
        }
        const uint4* gB = (const uint4*)(g_vb + ((long)tb*384 + dt*128)*256 + ch*64);
        for (int idx = tid; idx < 1024; idx += 256) {
            int i = idx >> 3, s = idx & 7;
            *(uint4*)(Bs + i*72 + s*8) = gB[i*32 + s];
        }
        __syncthreads();
        #pragma unroll
        for (int kt = 0; kt < 4; kt++) {
            uint32_t a[4][4], bf[4][2];
            #pragma unroll
            for (int r = 0; r < 4; r++) {
                uint32_t ad = baseA + (uint32_t)(((wn + r*16 + aRow)*72 + kt*16 + aK) * 2);
                LDMX4(a[r][0], a[r][1], a[r][2], a[r][3], ad);
            }
            #pragma unroll
            for (int c = 0; c < 4; c++) {
                uint32_t ad = baseB + (uint32_t)(((wm + c*8 + bRow)*72 + kt*16 + bK) * 2);
                LDMX2(bf[c][0], bf[c][1], ad);
            }
            #pragma unroll
            for (int r = 0; r < 4; r++)
                #pragma unroll
                for (int c = 0; c < 4; c++)
                    MMA16816(acc[r][c][0], acc[r][c][1], acc[r][c][2], acc[r][c][3],
                             a[r][0], a[r][1], a[r][2], a[r][3], bf[c][0], bf[c][1]);
        }
        __syncthreads();
    }

    #pragma unroll
    for (int r = 0; r < 4; r++) {
        int n = nt*128 + wn + r*16 + (lane >> 2);
        #pragma unroll
        for (int c = 0; c < 4; c++) {
            int d = dt*128 + wm + c*8 + (lane & 3)*2;
            float2 v0 = make_float2(acc[r][c][0], acc[r][c][1]);
            float2 v1 = make_float2(acc[r][c][2], acc[r][c][3]);
            *(float2*)(g_res + ((long)eb*256 + n)*384 + d)     = v0;
            *(float2*)(g_res + ((long)eb*256 + n + 8)*384 + d) = v1;
        }
    }
}

// ========== exact-fp32 linear via 3-split bf16 mma =========================
__global__ __launch_bounds__(256) void wmma_lin_kernel(
    const unsigned short* __restrict__ A3, const unsigned short* __restrict__ Bb,
    float* __restrict__ outF,
    const float* __restrict__ bias, const float* __restrict__ scale,
    const float* __restrict__ shift, int M, int K)
{
    __shared__ unsigned short As[3*128*40];
    __shared__ unsigned short Bs[128*40];
    int mt = blockIdx.x, nt = blockIdx.y, z = blockIdx.z;
    int tid = threadIdx.x, lane = tid & 31, warp = tid >> 5;
    int m0 = mt * 128;
    int wn = (warp >> 2) * 64, wm = (warp & 3) * 32;
    float acc[4][4][4] = {};
    uint32_t baseA = smem_u32(As), baseB = smem_u32(Bs);
    int aRow = lane & 15, aK = (lane >> 4) * 8;
    int bRow = lane & 7,  bK = ((lane >> 3) & 1) * 8;

    for (int k0 = 0; k0 < K; k0 += 32) {
        for (int idx = tid; idx < 1536; idx += 256) {
            int s = idx / 512, r = idx % 512;
            int i = r >> 2, p4 = r & 3;
            *(uint4*)(As + (s*128 + i)*40 + p4*8) =
                *(const uint4*)(A3 + ((long)s*M + m0 + i)*K + k0 + p4*8);
        }
        for (int idx = tid; idx < 512; idx += 256) {
            int i = idx >> 2, p4 = idx & 3;
            *(uint4*)(Bs + i*40 + p4*8) =
                *(const uint4*)(Bb + ((long)z*256 + nt*128 + i)*K + k0 + p4*8);
        }
        __syncthreads();
        #pragma unroll
        for (int kt = 0; kt < 2; kt++) {
            uint32_t bf[4][2];
            #pragma unroll
            for (int c = 0; c < 4; c++) {
                uint32_t ad = baseB + (uint32_t)(((wm + c*8 + bRow)*40 + kt*16 + bK) * 2);
                LDMX2(bf[c][0], bf[c][1], ad);
            }
            #pragma unroll
            for (int s = 0; s < 3; s++) {
                uint32_t a[4][4];
                #pragma unroll
                for (int r = 0; r < 4; r++) {
                    uint32_t ad = baseA + (uint32_t)(((s*128 + wn + r*16 + aRow)*40 + kt*16 + aK) * 2);
                    LDMX4(a[r][0], a[r][1], a[r][2], a[r][3], ad);
                }
                #pragma unroll
                for (int r = 0; r < 4; r++)
                    #pragma unroll
                    for (int c = 0; c < 4; c++)
                        MMA16816(acc[r][c][0], acc[r][c][1], acc[r][c][2], acc[r][c][3],
                                 a[r][0], a[r][1], a[r][2], a[r][3], bf[c][0], bf[c][1]);
            }
        }
        __syncthreads();
    }

    #pragma unroll
    for (int r = 0; r < 4; r++) {
        int m  = m0 + wn + r*16 + (lane >> 2);
        float bi0 = bias[m],   sc0 = scale[m]   * BNS, sh0 = shift[m];
        float bi1 = bias[m+8], sc1 = scale[m+8] * BNS, sh1 = shift[m+8];
        #pragma unroll
        for (int c = 0; c < 4; c++) {
            int n = nt*128 + wm + c*8 + (lane & 3)*2;
            float2 v0, v1;
            v0.x = (acc[r][c][0] + bi0) * sc0 + sh0;
            v0.y = (acc[r][c][1] + bi0) * sc0 + sh0;
            v1.x = (acc[r][c][2] + bi1) * sc1 + sh1;
            v1.y = (acc[r][c][3] + bi1) * sc1 + sh1;
            *(float2*)(outF + ((long)z*M + m)*256 + n)     = v0;
            *(float2*)(outF + ((long)z*M + m + 8)*256 + n) = v1;
        }
    }
}

// ================= helper kernels ==========================================
__global__ void wsplit3_kernel(const float* __restrict__ w, unsigned short* __restrict__ w3, int total)
{
    int i = blockIdx.x * 256 + threadIdx.x;
    if (i >= total) return;
    float x = w[i];
    __nv_bfloat16 h0 = __float2bfloat16(x);
    float r1 = x - __bfloat162float(h0);
    __nv_bfloat16 h1 = __float2bfloat16(r1);
    float r2 = r1 - __bfloat162float(h1);
    __nv_bfloat16 h2 = __float2bfloat16(r2);
    w3[i]             = __bfloat16_as_ushort(h0);
    w3[total + i]     = __bfloat16_as_ushort(h1);
    w3[2 * total + i] = __bfloat16_as_ushort(h2);
}

__global__ void combine_lif_kernel()
{
    long tid = (long)blockIdx.x * 256 + threadIdx.x;
    if (tid >= (long)8 * 256 * 384) return;
    int d = (int)(tid % 384);
    int n = (int)((tid / 384) % 256);
    int b = (int)(tid / (384 * 256));
    float y[4] = {0.f, 0.f, 0.f, 0.f};
    #pragma unroll
    for (int e = 0; e < 4; e++) {
        float mem = 0.f;
        #pragma unroll
        for (int t = 0; t < 4; t++) {
            int eb = e * 32 + t * 8 + b;
            float pre = g_res[((long)eb * 256 + n) * 384 + d];
            mem = mem + (pre - mem) * 0.5f;
            float sp = (mem >= 1.f) ? 1.f : 0.f;
            mem *= (1.f - sp);
            y[t] = fmaf(g_w[((t * 8 + b) * 4 + e) * 256 + n], sp, y[t]);
        }
    }
    #pragma unroll
    for (int t = 0; t < 4; t++)
        g_yb[((long)(t * 8 + b) * 256 + n) * 384 + d] =
            __bfloat16_as_ushort(__float2bfloat16(y[t]));
}

__global__ void transpose_m_kernel()
{
    __shared__ unsigned short tile[32][33];
    int c0 = blockIdx.x * 32, n0 = blockIdx.y * 32, tb = blockIdx.z;
    int tx = threadIdx.x & 31, ty = threadIdx.x >> 5;
    #pragma unroll
    for (int p = 0; p < 4; p++) {
        int c = c0 + ty + p*8;
        tile[ty + p*8][tx] = __bfloat16_as_ushort(
            __float2bfloat16(g_m[((long)tb*1024 + c)*256 + n0 + tx]));
    }
    __syncthreads();
    #pragma unroll
    for (int p = 0; p < 4; p++) {
        int n = n0 + ty + p*8;
        g_mb[((long)tb*256 + n)*1024 + c0 + tx] = tile[tx][ty + p*8];
    }
}

__global__ void dwconv_gate_kernel(const float* __restrict__ dw_w, const float* __restrict__ dw_b,
                                   const float* __restrict__ dw_g, const float* __restrict__ dw_be)
{
    int tid = blockIdx.x * 256 + threadIdx.x;
    if (tid >= 8 * 1024 * 256) return;
    int n  = tid & 255;
    int c  = (tid >> 8) & 1023;
    int b  = tid >> 18;
    int hh = n >> 4, ww = n & 15;
    float wk[9];
    #pragma unroll
    for (int i = 0; i < 9; i++) wk[i] = dw_w[c * 9 + i];
    float bi = dw_b[c], sc = dw_g[c] * BNS, sh = dw_be[c];
    float mem = 0.f;
    #pragma unroll
    for (int t = 0; t < 4; t++) {
        int tb = t * 8 + b;
        const float* x1 = g_h + ((long)tb * 2048 + c) * 256;
        float acc = bi;
        #pragma unroll
        for (int di = 0; di < 3; di++) {
            int yy = hh + di - 1;
            if (yy < 0 || yy > 15) continue;
            #pragma unroll
            for (int dj = 0; dj < 3; dj++) {
                int xx = ww + dj - 1;
                if (xx < 0 || xx > 15) continue;
                acc = fmaf(wk[di * 3 + dj], x1[yy * 16 + xx], acc);
            }
        }
        float pre = acc * sc + sh;
        mem = mem + (pre - mem) * 0.5f;
        float sp = (mem >= 1.f) ? 1.f : 0.f;
        mem *= (1.f - sp);
        float x2 = g_h[((long)tb * 2048 + 1024 + c) * 256 + n];
        g_m[((long)tb * 1024 + c) * 256 + n] = sp * x2;
    }
}

// ===========================================================================
extern "C" void kernel_launch(void* const* d_in, const int* in_sizes, int n_in,
                              void* d_out, int out_size)
{
    const float* x         = (const float*)d_in[0];
    const float* k_w       = (const float*)d_in[2];
    const float* v_w       = (const float*)d_in[3];
    const float* router_w  = (const float*)d_in[4];
    const float* router_b  = (const float*)d_in[5];
    const float* router_g  = (const float*)d_in[6];
    const float* router_be = (const float*)d_in[7];
    const float* exp_w     = (const float*)d_in[8];
    const float* exp_g     = (const float*)d_in[9];
    const float* exp_b     = (const float*)d_in[10];
    const float* proj_w    = (const float*)d_in[11];
    const float* proj_b    = (const float*)d_in[12];
    const float* proj_g    = (const float*)d_in[13];
    const float* proj_be   = (const float*)d_in[14];
    const float* fc1_w     = (const float*)d_in[15];
    const float* fc1_b     = (const float*)d_in[16];
    const float* fc1_g     = (const float*)d_in[17];
    const float* fc1_be    = (const float*)d_in[18];
    const float* dw_w      = (const float*)d_in[19];
    const float* dw_b      = (const float*)d_in[20];
    const float* dw_g      = (const float*)d_in[21];
    const float* dw_be     = (const float*)d_in[22];
    const float* fc2_w     = (const float*)d_in[23];
    const float* fc2_b     = (const float*)d_in[24];
    const float* fc2_g     = (const float*)d_in[25];
    const float* fc2_be    = (const float*)d_in[26];
    float* out = (float*)d_out;

    float *pk, *pv, *pw, *pp, *pxr, *ph, *pm, *pf2, *pres;
    unsigned short *pqb, *pkb, *pvb, *pyb, *pmb, *pw3a, *pw3b;
    cudaGetSymbolAddress((void**)&pk,   g_k);
    cudaGetSymbolAddress((void**)&pv,   g_v);
    cudaGetSymbolAddress((void**)&pw,   g_w);
    cudaGetSymbolAddress((void**)&pres, g_res);
    cudaGetSymbolAddress((void**)&pp,   g_p);
    cudaGetSymbolAddress((void**)&pxr,  g_xr);
    cudaGetSymbolAddress((void**)&ph,   g_h);
    cudaGetSymbolAddress((void**)&pm,   g_m);
    cudaGetSymbolAddress((void**)&pf2,  g_f2);
    cudaGetSymbolAddress((void**)&pqb,  g_qb);
    cudaGetSymbolAddress((void**)&pkb,  g_kb);
    cudaGetSymbolAddress((void**)&pvb,  g_vb);
    cudaGetSymbolAddress((void**)&pyb,  g_yb);
    cudaGetSymbolAddress((void**)&pmb,  g_mb);
    cudaGetSymbolAddress((void**)&pw3a, g_w3a);
    cudaGetSymbolAddress((void**)&pw3b, g_w3b);

    cudaFuncSetAttribute(attn_mma_kernel, cudaFuncAttributeMaxDynamicSharedMemorySize, 53248);
    cudaFuncSetAttribute(gemm_zs_kernel<2>, cudaFuncAttributeMaxDynamicSharedMemorySize, 39168);
    cudaFuncSetAttribute(gemm_z4lif_kernel<1>, cudaFuncAttributeMaxDynamicSharedMemorySize, 65280);
    cudaFuncSetAttribute(gemm_z4lif_kernel<2>, cudaFuncAttributeMaxDynamicSharedMemorySize, 65280);

    const long XB = 384 * 256;
    dim3 blk(256);
    const int SM2 = 39168, SM4 = 65280;

    // weight splits
    wsplit3_kernel<<<(384*384+255)/256,blk>>>(proj_w, pw3a, 384*384);
    wsplit3_kernel<<<(384*1024+255)/256,blk>>>(fc2_w, pw3b, 384*1024);

    // --- SSA pre-activations ---
    gemm_zs_kernel<2><<<dim3(4,2,16),blk,SM2>>>(k_w,0, x,XB,
        pk, nullptr,nullptr,nullptr,0, 96,384);
    gemm_zs_kernel<2><<<dim3(4,6,16),blk,SM2>>>(v_w,0, x,XB,
        pv, nullptr,nullptr,nullptr,0, 384,384);
    gemm_zs_kernel<2><<<dim3(4,1,16),blk,SM2>>>(router_w,0, x,XB,
        pw, router_b,router_g,router_be,0, 4,384);
    // q: z4 GEMM + fused LIF -> bf16 spikes directly in mma layout
    gemm_z4lif_kernel<2><<<dim3(4,2,32),blk,SM4>>>(exp_w,(long)96*384, x,XB,
        nullptr,pqb, nullptr,exp_g,exp_b,96, 96,384);

    // --- remaining LIF -> bf16 spikes ---
    lif_k_kernel<<<(8*96*256+255)/256,blk>>>();
    lif_v_kernel<<<(8*384*256+255)/256,blk>>>();
    lif4_kernel<<<(8*256+255)/256,blk>>>((float4*)pw, 256);

    // --- tensor-core attention ---
    attn_mma_kernel<<<dim3(2,2,128),blk,53248>>>();
    res_mma_kernel<<<dim3(3,2,128),blk>>>();

    // fused res-LIF + combine -> bf16 y
    combine_lif_kernel<<<(8*256*384+255)/256,blk>>>();

    // proj on tensor cores -> pre-acts; fused LIF+residual: xr = x + spike(p)
    wmma_lin_kernel<<<dim3(3,2,32),blk>>>(pw3a, pyb, pp, proj_b, proj_g, proj_be, 384, 384);
    lif4_add_kernel<<<(8*24576+255)/256,blk>>>((const float4*)pp, (const float4*)x,
                                               (float4*)pxr, 24576);

    // --- MLP ---
    // fc1: z4 GEMM + fused LIF -> fp32 spikes directly to g_h
    gemm_z4lif_kernel<1><<<dim3(4,32,8),blk,SM4>>>(fc1_w,0, pxr,XB,
        ph,nullptr, fc1_b,fc1_g,fc1_be,0, 2048,384);
    dwconv_gate_kernel<<<(8*1024*256+255)/256,blk>>>(dw_w, dw_b, dw_g, dw_be);
    transpose_m_kernel<<<dim3(32,8,32),blk>>>();

    // fc2 on tensor cores -> pre-acts; fused LIF+residual: out = xr + spike(f2)
    wmma_lin_kernel<<<dim3(3,2,32),blk>>>(pw3b, pmb, pf2, fc2_b, fc2_g, fc2_be, 384, 1024);
    lif4_add_kernel<<<(8*24576+255)/256,blk>>>((const float4*)pf2, (const float4*)pxr,
                                               (float4*)out, 24576);
}